// round 11
// baseline (speedup 1.0000x reference)
#include <cuda_runtime.h>

// R11: R2 (best measured: 45.5us) with three slot-count reductions and
// nothing else changed:
//  1) sincosf/sinf -> __sincosf/__sinf intrinsics (prologue trig ~10x fewer slots)
//  2) v pre-projected through Wq at staging: loop accumulates p*(v@Wq)
//     (3 packed chains instead of 4); epilogue o@Wq disappears
//  3) logits stored directly to gmem (no smem staging / extra barrier)
// Structure, tiling, packed fma.rn.f32x2 loop, max-free softmax: identical to R2.

#define T 64
#define BPB 4
#define NTHREADS (BPB * T)
#define VOCAB 10

typedef unsigned long long u64;

__device__ __forceinline__ float ex2f(float x) {
    float y; asm("ex2.approx.ftz.f32 %0, %1;" : "=f"(y) : "f"(x)); return y;
}
__device__ __forceinline__ float rcpf(float x) {
    float y; asm("rcp.approx.ftz.f32 %0, %1;" : "=f"(y) : "f"(x)); return y;
}
__device__ __forceinline__ u64 pack2(float lo, float hi) {
    u64 r; asm("mov.b64 %0, {%1, %2};" : "=l"(r) : "f"(lo), "f"(hi)); return r;
}
__device__ __forceinline__ void unpack2(u64 v, float& lo, float& hi) {
    asm("mov.b64 {%0, %1}, %2;" : "=f"(lo), "=f"(hi) : "l"(v));
}
__device__ __forceinline__ u64 fma2(u64 a, u64 b, u64 c) {
    u64 d; asm("fma.rn.f32x2 %0, %1, %2, %3;" : "=l"(d) : "l"(a), "l"(b), "l"(c)); return d;
}
__device__ __forceinline__ u64 mul2(u64 a, u64 b) {
    u64 d; asm("mul.rn.f32x2 %0, %1, %2;" : "=l"(d) : "l"(a), "l"(b)); return d;
}
__device__ __forceinline__ u64 add2(u64 a, u64 b) {
    u64 d; asm("add.rn.f32x2 %0, %1, %2;" : "=l"(d) : "l"(a), "l"(b)); return d;
}

__global__ __launch_bounds__(NTHREADS)
void adder_model_kernel(
    const int* __restrict__ idx,
    const float* __restrict__ pA,
    const float* __restrict__ pStart,
    const float* __restrict__ pStride,
    const float* __restrict__ w_ln1,
    const float* __restrict__ w_ln2,
    const float* __restrict__ w_lnf,
    const float* __restrict__ w_qn,
    const float* __restrict__ Wq,
    const float* __restrict__ Wk,
    const float* __restrict__ Wg,
    const float* __restrict__ Wu,
    const float* __restrict__ Wd,
    float* __restrict__ out)
{
    // pair-interleaved: kA[b][i] = {pack(k0[2i],k0[2i+1]), pack(k1[2i],k1[2i+1])}
    __shared__ ulonglong2 kA[BPB][T / 2];
    __shared__ ulonglong2 kB[BPB][T / 2];
    __shared__ ulonglong2 vA[BPB][T / 2];   // (vq0 pair, vq1 pair)
    __shared__ u64        vC[BPB][T / 2];   // vq2 pair
    __shared__ float2 table_sh[VOCAB];

    const int tid   = threadIdx.x;
    const int local = tid >> 6;          // batch within block
    const int t     = tid & 63;          // token
    const int b     = blockIdx.x * BPB + local;

    const float A       = pA[0];
    const float astart  = pStart[0];
    const float astride = pStride[0];

    // digit table (shared across block)
    if (tid < VOCAB) {
        float s, c;
        __sincosf(astart + (float)tid * astride, &s, &c);
        table_sh[tid] = make_float2(A * c, A * s);
    }

    // ---- embedding ----
    const int dig = idx[b * T + t];
    float sa, ca;
    __sincosf(astart + (float)dig * astride, &sa, &ca);
    float x0 = A * ca;
    float x1 = A * sa;
    float x2 = __sinf((float)t * 1.0e-4f);   // pe = sin(t * exp(-ln 1e4))

    // ---- RMS ln1 ----
    float ms = (x0 * x0 + x1 * x1 + x2 * x2) * (1.0f / 3.0f) + 1e-6f;
    float r  = rsqrtf(ms);
    float h0 = x0 * r * w_ln1[0];
    float h1 = x1 * r * w_ln1[1];
    float h2 = x2 * r * w_ln1[2];

    // ---- q/k/v projections (v shares the Wk product) ----
    float qr[4], kv[4];
#pragma unroll
    for (int j = 0; j < 4; ++j) {
        qr[j] = h0 * Wq[j * 3 + 0] + h1 * Wq[j * 3 + 1] + h2 * Wq[j * 3 + 2];
        kv[j] = h0 * Wk[j * 3 + 0] + h1 * Wk[j * 3 + 1] + h2 * Wk[j * 3 + 2];
    }

    // v pre-projected through Wq: vq[d] = sum_j v[j] * Wq[j*3+d]
    float vq0 = kv[0]*Wq[0] + kv[1]*Wq[3] + kv[2]*Wq[6] + kv[3]*Wq[9];
    float vq1 = kv[0]*Wq[1] + kv[1]*Wq[4] + kv[2]*Wq[7] + kv[3]*Wq[10];
    float vq2 = kv[0]*Wq[2] + kv[1]*Wq[5] + kv[2]*Wq[8] + kv[3]*Wq[11];

    const float wq0 = w_qn[0], wq1 = w_qn[1], wq2 = w_qn[2], wq3 = w_qn[3];
    float msq = (qr[0]*qr[0] + qr[1]*qr[1] + qr[2]*qr[2] + qr[3]*qr[3]) * 0.25f + 1e-6f;
    float rq  = rsqrtf(msq);
    float q0 = qr[0] * rq * wq0, q1 = qr[1] * rq * wq1;
    float q2 = qr[2] * rq * wq2, q3 = qr[3] * rq * wq3;

    float msk = (kv[0]*kv[0] + kv[1]*kv[1] + kv[2]*kv[2] + kv[3]*kv[3]) * 0.25f + 1e-6f;
    float rk  = rsqrtf(msk);
    float k0 = kv[0] * rk * wq0, k1 = kv[1] * rk * wq1;
    float k2 = kv[2] * rk * wq2, k3 = kv[3] * rk * wq3;

    // ---- RoPE (theta=3, HD=4 -> inv_freq = {1, 3^-0.5}) ----
    float s0, c0, s1, c1;
    __sincosf((float)t, &s0, &c0);
    __sincosf((float)t * 0.57735026918962576f, &s1, &c1);

    float Q0 = q0 * c0 - q1 * s0, Q1 = q0 * s0 + q1 * c0;
    float Q2 = q2 * c1 - q3 * s1, Q3 = q2 * s1 + q3 * c1;
    float K0 = k0 * c0 - k1 * s0, K1 = k0 * s0 + k1 * c0;
    float K2 = k2 * c1 - k3 * s1, K3 = k2 * s1 + k3 * c1;

    // fold softmax scale (HD^-0.5 = 0.5) and log2(e) into q
    const float SC = 0.5f * 1.4426950408889634f;
    Q0 *= SC; Q1 *= SC; Q2 *= SC; Q3 *= SC;

    // ---- stage k/vq into pair-interleaved smem ----
    {
        const int i = t >> 1, lane = t & 1;
        float* a = (float*)&kA[local][i]; a[lane] = K0; a[2 + lane] = K1;
        float* bb = (float*)&kB[local][i]; bb[lane] = K2; bb[2 + lane] = K3;
        float* c = (float*)&vA[local][i]; c[lane] = vq0; c[2 + lane] = vq1;
        float* d = (float*)&vC[local][i]; d[lane] = vq2;
    }
    __syncthreads();

    // ---- causal attention, packed 2-wide, max-free single pass ----
    const u64 Q0d = pack2(Q0, Q0), Q1d = pack2(Q1, Q1);
    const u64 Q2d = pack2(Q2, Q2), Q3d = pack2(Q3, Q3);

    u64 sum2 = 0ULL, c0a = 0ULL, c1a = 0ULL, c2a = 0ULL;
    const int np = (t + 1) >> 1;      // full pairs: s in [0, 2*np)
#pragma unroll 4
    for (int i = 0; i < np; ++i) {
        const ulonglong2 ka = kA[local][i];
        const ulonglong2 kb = kB[local][i];
        const u64 sc2 = fma2(Q0d, ka.x, fma2(Q1d, ka.y, fma2(Q2d, kb.x, mul2(Q3d, kb.y))));
        float sl, sh; unpack2(sc2, sl, sh);
        const u64 p2 = pack2(ex2f(sl), ex2f(sh));
        sum2 = add2(sum2, p2);
        const ulonglong2 va = vA[local][i];
        const u64 vc = vC[local][i];
        c0a = fma2(p2, va.x, c0a);
        c1a = fma2(p2, va.y, c1a);
        c2a = fma2(p2, vc,   c2a);
    }
    float sl, sh, a0, a1, a2, tl, th;
    unpack2(sum2, sl, sh); float sum = sl + sh;
    unpack2(c0a, tl, th); a0 = tl + th;
    unpack2(c1a, tl, th); a1 = tl + th;
    unpack2(c2a, tl, th); a2 = tl + th;

    if (!(t & 1)) {                   // leftover s = t (self-attention term)
        const float sc = Q0 * K0 + Q1 * K1 + Q2 * K2 + Q3 * K3;
        const float p  = ex2f(sc);
        sum += p;
        a0 += p * vq0; a1 += p * vq1; a2 += p * vq2;
    }

    const float inv = rcpf(sum);
    // x += (sum p * v@Wq) / sum  == out @ Wq
    x0 += a0 * inv;
    x1 += a1 * inv;
    x2 += a2 * inv;

    // ---- RMS ln2 + SwiGLU FFN ----
    ms = (x0 * x0 + x1 * x1 + x2 * x2) * (1.0f / 3.0f) + 1e-6f;
    r  = rsqrtf(ms);
    h0 = x0 * r * w_ln2[0];
    h1 = x1 * r * w_ln2[1];
    h2 = x2 * r * w_ln2[2];

    const float g0 = h0 * Wg[0] + h1 * Wg[1] + h2 * Wg[2];
    const float g1 = h0 * Wg[3] + h1 * Wg[4] + h2 * Wg[5];
    const float u0 = h0 * Wu[0] + h1 * Wu[1] + h2 * Wu[2];
    const float u1 = h0 * Wu[3] + h1 * Wu[4] + h2 * Wu[5];

    const float LOG2E = 1.4426950408889634f;
    const float m0 = g0 * u0 * rcpf(1.0f + ex2f(-g0 * LOG2E));  // silu(g0)*u0
    const float m1 = g1 * u1 * rcpf(1.0f + ex2f(-g1 * LOG2E));

    x0 += m0 * Wd[0] + m1 * Wd[1];
    x1 += m0 * Wd[2] + m1 * Wd[3];
    x2 += m0 * Wd[4] + m1 * Wd[5];

    // ---- final RMS (only first two channels feed the logits) ----
    ms = (x0 * x0 + x1 * x1 + x2 * x2) * (1.0f / 3.0f) + 1e-6f;
    r  = rsqrtf(ms);
    const float f0 = x0 * r * w_lnf[0];
    const float f1 = x1 * r * w_lnf[1];

    // ---- logits: direct gmem stores (5 x STG.64 per thread) ----
    float2* dst = (float2*)(out + (size_t)(b * T + t) * VOCAB);
#pragma unroll
    for (int j = 0; j < 5; ++j) {
        const float2 ta = table_sh[2*j], tb = table_sh[2*j + 1];
        dst[j] = make_float2(f0 * ta.x + f1 * ta.y, f0 * tb.x + f1 * tb.y);
    }
}

extern "C" void kernel_launch(void* const* d_in, const int* in_sizes, int n_in,
                              void* d_out, int out_size)
{
    const int*   idx     = (const int*)  d_in[0];
    const float* arc_A   = (const float*)d_in[1];
    const float* arc_st  = (const float*)d_in[2];
    const float* arc_sd  = (const float*)d_in[3];
    const float* w_ln1   = (const float*)d_in[4];
    const float* w_ln2   = (const float*)d_in[5];
    const float* w_lnf   = (const float*)d_in[6];
    const float* w_qn    = (const float*)d_in[7];
    const float* Wq      = (const float*)d_in[8];
    const float* Wk      = (const float*)d_in[9];
    const float* Wg      = (const float*)d_in[10];
    const float* Wu      = (const float*)d_in[11];
    const float* Wd      = (const float*)d_in[12];
    float* out = (float*)d_out;

    const int B = in_sizes[0] / T;           // 16384
    const int grid = B / BPB;                // 4096 blocks
    adder_model_kernel<<<grid, NTHREADS>>>(idx, arc_A, arc_st, arc_sd,
                                           w_ln1, w_ln2, w_lnf, w_qn,
                                           Wq, Wk, Wg, Wu, Wd, out);
}

// round 12
// speedup vs baseline: 1.5369x; 1.5369x over previous
#include <cuda_runtime.h>

// R12: R2 (best measured) + the two verified-safe slot reductions from R11
// (intrinsic trig, v pre-projected through Wq -> 3 accumulator chains),
// with R2's smem-staged fully-coalesced logits store RESTORED (R11's direct
// scattered STGs caused ~40 sectors/warp-store in LSU replays -> +15us).

#define T 64
#define BPB 4
#define NTHREADS (BPB * T)
#define VOCAB 10

typedef unsigned long long u64;

__device__ __forceinline__ float ex2f(float x) {
    float y; asm("ex2.approx.ftz.f32 %0, %1;" : "=f"(y) : "f"(x)); return y;
}
__device__ __forceinline__ float rcpf(float x) {
    float y; asm("rcp.approx.ftz.f32 %0, %1;" : "=f"(y) : "f"(x)); return y;
}
__device__ __forceinline__ u64 pack2(float lo, float hi) {
    u64 r; asm("mov.b64 %0, {%1, %2};" : "=l"(r) : "f"(lo), "f"(hi)); return r;
}
__device__ __forceinline__ void unpack2(u64 v, float& lo, float& hi) {
    asm("mov.b64 {%0, %1}, %2;" : "=f"(lo), "=f"(hi) : "l"(v));
}
__device__ __forceinline__ u64 fma2(u64 a, u64 b, u64 c) {
    u64 d; asm("fma.rn.f32x2 %0, %1, %2, %3;" : "=l"(d) : "l"(a), "l"(b), "l"(c)); return d;
}
__device__ __forceinline__ u64 mul2(u64 a, u64 b) {
    u64 d; asm("mul.rn.f32x2 %0, %1, %2;" : "=l"(d) : "l"(a), "l"(b)); return d;
}
__device__ __forceinline__ u64 add2(u64 a, u64 b) {
    u64 d; asm("add.rn.f32x2 %0, %1, %2;" : "=l"(d) : "l"(a), "l"(b)); return d;
}

__global__ __launch_bounds__(NTHREADS)
void adder_model_kernel(
    const int* __restrict__ idx,
    const float* __restrict__ pA,
    const float* __restrict__ pStart,
    const float* __restrict__ pStride,
    const float* __restrict__ w_ln1,
    const float* __restrict__ w_ln2,
    const float* __restrict__ w_lnf,
    const float* __restrict__ w_qn,
    const float* __restrict__ Wq,
    const float* __restrict__ Wk,
    const float* __restrict__ Wg,
    const float* __restrict__ Wu,
    const float* __restrict__ Wd,
    float* __restrict__ out)
{
    // pair-interleaved: kA[b][i] = {pack(k0[2i],k0[2i+1]), pack(k1[2i],k1[2i+1])}
    __shared__ ulonglong2 kA[BPB][T / 2];
    __shared__ ulonglong2 kB[BPB][T / 2];
    __shared__ ulonglong2 vA[BPB][T / 2];   // (vq0 pair, vq1 pair)
    __shared__ u64        vC[BPB][T / 2];   // vq2 pair
    __shared__ float2 table_sh[VOCAB];
    __shared__ float  logits_sh[BPB * T * VOCAB];

    const int tid   = threadIdx.x;
    const int local = tid >> 6;          // batch within block
    const int t     = tid & 63;          // token
    const int b     = blockIdx.x * BPB + local;

    const float A       = pA[0];
    const float astart  = pStart[0];
    const float astride = pStride[0];

    // digit table (shared across block)
    if (tid < VOCAB) {
        float s, c;
        __sincosf(astart + (float)tid * astride, &s, &c);
        table_sh[tid] = make_float2(A * c, A * s);
    }

    // ---- embedding ----
    const int dig = idx[b * T + t];
    float sa, ca;
    __sincosf(astart + (float)dig * astride, &sa, &ca);
    float x0 = A * ca;
    float x1 = A * sa;
    float x2 = __sinf((float)t * 1.0e-4f);   // pe = sin(t * exp(-ln 1e4))

    // ---- RMS ln1 ----
    float ms = (x0 * x0 + x1 * x1 + x2 * x2) * (1.0f / 3.0f) + 1e-6f;
    float r  = rsqrtf(ms);
    float h0 = x0 * r * w_ln1[0];
    float h1 = x1 * r * w_ln1[1];
    float h2 = x2 * r * w_ln1[2];

    // ---- q/k/v projections (v shares the Wk product) ----
    float qr[4], kv[4];
#pragma unroll
    for (int j = 0; j < 4; ++j) {
        qr[j] = h0 * Wq[j * 3 + 0] + h1 * Wq[j * 3 + 1] + h2 * Wq[j * 3 + 2];
        kv[j] = h0 * Wk[j * 3 + 0] + h1 * Wk[j * 3 + 1] + h2 * Wk[j * 3 + 2];
    }

    // v pre-projected through Wq: vq[d] = sum_j v[j] * Wq[j*3+d]
    const float vq0 = kv[0]*Wq[0] + kv[1]*Wq[3] + kv[2]*Wq[6] + kv[3]*Wq[9];
    const float vq1 = kv[0]*Wq[1] + kv[1]*Wq[4] + kv[2]*Wq[7] + kv[3]*Wq[10];
    const float vq2 = kv[0]*Wq[2] + kv[1]*Wq[5] + kv[2]*Wq[8] + kv[3]*Wq[11];

    const float wq0 = w_qn[0], wq1 = w_qn[1], wq2 = w_qn[2], wq3 = w_qn[3];
    float msq = (qr[0]*qr[0] + qr[1]*qr[1] + qr[2]*qr[2] + qr[3]*qr[3]) * 0.25f + 1e-6f;
    float rq  = rsqrtf(msq);
    float q0 = qr[0] * rq * wq0, q1 = qr[1] * rq * wq1;
    float q2 = qr[2] * rq * wq2, q3 = qr[3] * rq * wq3;

    float msk = (kv[0]*kv[0] + kv[1]*kv[1] + kv[2]*kv[2] + kv[3]*kv[3]) * 0.25f + 1e-6f;
    float rk  = rsqrtf(msk);
    float k0 = kv[0] * rk * wq0, k1 = kv[1] * rk * wq1;
    float k2 = kv[2] * rk * wq2, k3 = kv[3] * rk * wq3;

    // ---- RoPE (theta=3, HD=4 -> inv_freq = {1, 3^-0.5}) ----
    float s0, c0, s1, c1;
    __sincosf((float)t, &s0, &c0);
    __sincosf((float)t * 0.57735026918962576f, &s1, &c1);

    float Q0 = q0 * c0 - q1 * s0, Q1 = q0 * s0 + q1 * c0;
    float Q2 = q2 * c1 - q3 * s1, Q3 = q2 * s1 + q3 * c1;
    float K0 = k0 * c0 - k1 * s0, K1 = k0 * s0 + k1 * c0;
    float K2 = k2 * c1 - k3 * s1, K3 = k2 * s1 + k3 * c1;

    // fold softmax scale (HD^-0.5 = 0.5) and log2(e) into q
    const float SC = 0.5f * 1.4426950408889634f;
    Q0 *= SC; Q1 *= SC; Q2 *= SC; Q3 *= SC;

    // ---- stage k/vq into pair-interleaved smem ----
    {
        const int i = t >> 1, lane = t & 1;
        float* a = (float*)&kA[local][i]; a[lane] = K0; a[2 + lane] = K1;
        float* bb = (float*)&kB[local][i]; bb[lane] = K2; bb[2 + lane] = K3;
        float* c = (float*)&vA[local][i]; c[lane] = vq0; c[2 + lane] = vq1;
        float* d = (float*)&vC[local][i]; d[lane] = vq2;
    }
    __syncthreads();

    // ---- causal attention, packed 2-wide, max-free single pass ----
    const u64 Q0d = pack2(Q0, Q0), Q1d = pack2(Q1, Q1);
    const u64 Q2d = pack2(Q2, Q2), Q3d = pack2(Q3, Q3);

    u64 sum2 = 0ULL, c0a = 0ULL, c1a = 0ULL, c2a = 0ULL;
    const int np = (t + 1) >> 1;      // full pairs: s in [0, 2*np)
#pragma unroll 4
    for (int i = 0; i < np; ++i) {
        const ulonglong2 ka = kA[local][i];
        const ulonglong2 kb = kB[local][i];
        const u64 sc2 = fma2(Q0d, ka.x, fma2(Q1d, ka.y, fma2(Q2d, kb.x, mul2(Q3d, kb.y))));
        float sl, sh; unpack2(sc2, sl, sh);
        const u64 p2 = pack2(ex2f(sl), ex2f(sh));
        sum2 = add2(sum2, p2);
        const ulonglong2 va = vA[local][i];
        const u64 vc = vC[local][i];
        c0a = fma2(p2, va.x, c0a);
        c1a = fma2(p2, va.y, c1a);
        c2a = fma2(p2, vc,   c2a);
    }
    float sl, sh, a0, a1, a2, tl, th;
    unpack2(sum2, sl, sh); float sum = sl + sh;
    unpack2(c0a, tl, th); a0 = tl + th;
    unpack2(c1a, tl, th); a1 = tl + th;
    unpack2(c2a, tl, th); a2 = tl + th;

    if (!(t & 1)) {                   // leftover s = t (self-attention term)
        const float sc = Q0 * K0 + Q1 * K1 + Q2 * K2 + Q3 * K3;
        const float p  = ex2f(sc);
        sum += p;
        a0 += p * vq0; a1 += p * vq1; a2 += p * vq2;
    }

    const float inv = rcpf(sum);
    // x += (sum p * v@Wq) / sum  == out @ Wq
    x0 += a0 * inv;
    x1 += a1 * inv;
    x2 += a2 * inv;

    // ---- RMS ln2 + SwiGLU FFN ----
    ms = (x0 * x0 + x1 * x1 + x2 * x2) * (1.0f / 3.0f) + 1e-6f;
    r  = rsqrtf(ms);
    h0 = x0 * r * w_ln2[0];
    h1 = x1 * r * w_ln2[1];
    h2 = x2 * r * w_ln2[2];

    const float g0 = h0 * Wg[0] + h1 * Wg[1] + h2 * Wg[2];
    const float g1 = h0 * Wg[3] + h1 * Wg[4] + h2 * Wg[5];
    const float u0 = h0 * Wu[0] + h1 * Wu[1] + h2 * Wu[2];
    const float u1 = h0 * Wu[3] + h1 * Wu[4] + h2 * Wu[5];

    const float LOG2E = 1.4426950408889634f;
    const float m0 = g0 * u0 * rcpf(1.0f + ex2f(-g0 * LOG2E));  // silu(g0)*u0
    const float m1 = g1 * u1 * rcpf(1.0f + ex2f(-g1 * LOG2E));

    x0 += m0 * Wd[0] + m1 * Wd[1];
    x1 += m0 * Wd[2] + m1 * Wd[3];
    x2 += m0 * Wd[4] + m1 * Wd[5];

    // ---- final RMS (only first two channels feed the logits) ----
    ms = (x0 * x0 + x1 * x1 + x2 * x2) * (1.0f / 3.0f) + 1e-6f;
    r  = rsqrtf(ms);
    const float f0 = x0 * r * w_lnf[0];
    const float f1 = x1 * r * w_lnf[1];

    // ---- logits -> smem staging ----
    float* lg = &logits_sh[(local * T + t) * VOCAB];
#pragma unroll
    for (int vv = 0; vv < VOCAB; ++vv) {
        const float2 tb = table_sh[vv];
        lg[vv] = f0 * tb.x + f1 * tb.y;
    }
    __syncthreads();

    // ---- coalesced store: block owns a contiguous 2560-float span ----
    float2* dst2 = (float2*)(out + (size_t)blockIdx.x * (BPB * T * VOCAB));
    const float2* src2 = (const float2*)logits_sh;
#pragma unroll
    for (int i = tid; i < BPB * T * VOCAB / 2; i += NTHREADS)
        dst2[i] = src2[i];
}

extern "C" void kernel_launch(void* const* d_in, const int* in_sizes, int n_in,
                              void* d_out, int out_size)
{
    const int*   idx     = (const int*)  d_in[0];
    const float* arc_A   = (const float*)d_in[1];
    const float* arc_st  = (const float*)d_in[2];
    const float* arc_sd  = (const float*)d_in[3];
    const float* w_ln1   = (const float*)d_in[4];
    const float* w_ln2   = (const float*)d_in[5];
    const float* w_lnf   = (const float*)d_in[6];
    const float* w_qn    = (const float*)d_in[7];
    const float* Wq      = (const float*)d_in[8];
    const float* Wk      = (const float*)d_in[9];
    const float* Wg      = (const float*)d_in[10];
    const float* Wu      = (const float*)d_in[11];
    const float* Wd      = (const float*)d_in[12];
    float* out = (float*)d_out;

    const int B = in_sizes[0] / T;           // 16384
    const int grid = B / BPB;                // 4096 blocks
    adder_model_kernel<<<grid, NTHREADS>>>(idx, arc_A, arc_st, arc_sd,
                                           w_ln1, w_ln2, w_lnf, w_qn,
                                           Wq, Wk, Wg, Wu, Wd, out);
}